// round 7
// baseline (speedup 1.0000x reference)
#include <cuda_runtime.h>
#include <math.h>

#define IN_DIM   512
#define HID      512
#define NSM      148
#define GRID1    NSM            // 148 blocks, exactly 1 per SM
#define BLK1     1024           // 8 row-workers of 128 threads each
#define WPB      8
#define NWORK    (GRID1 * WPB)  // 1184 row workers

// Per-block partial column sums after intra-block reduce. 303 KB.
__device__ float g_scratch[GRID1 * IN_DIM];

// ---------------------------------------------------------------------------
// Kernel 1: partial column sums of X (n_rows x 512).
// 148 blocks x 1024 threads: 8 independent 128-thread row-workers per block,
// each float4-coalesced over one row, 8-way unrolled grid-stride (stride
// 1184) -> 8 LDG.128 in flight per thread, 32 warps/SM. Intra-block smem
// reduce -> scratch is only 148 rows, shrinking the finalize working set 3x.
// ---------------------------------------------------------------------------
__global__ void __launch_bounds__(BLK1, 1) colsum_kernel(const float* __restrict__ X, int n_rows) {
    const int t  = threadIdx.x;
    const int c4 = t & 127;          // float4 column 0..127
    const int g  = t >> 7;           // row-worker group 0..7
    const float4* __restrict__ Xv = (const float4*)X;
    const int S = NWORK;

    float4 acc0 = make_float4(0.f, 0.f, 0.f, 0.f);
    float4 acc1 = make_float4(0.f, 0.f, 0.f, 0.f);
    float4 acc2 = make_float4(0.f, 0.f, 0.f, 0.f);
    float4 acc3 = make_float4(0.f, 0.f, 0.f, 0.f);

    int r = blockIdx.x * WPB + g;
    for (; r + 7 * S < n_rows; r += 8 * S) {
        float4 v0 = Xv[(size_t)(r        ) * 128 + c4];
        float4 v1 = Xv[(size_t)(r + 1 * S) * 128 + c4];
        float4 v2 = Xv[(size_t)(r + 2 * S) * 128 + c4];
        float4 v3 = Xv[(size_t)(r + 3 * S) * 128 + c4];
        float4 v4 = Xv[(size_t)(r + 4 * S) * 128 + c4];
        float4 v5 = Xv[(size_t)(r + 5 * S) * 128 + c4];
        float4 v6 = Xv[(size_t)(r + 6 * S) * 128 + c4];
        float4 v7 = Xv[(size_t)(r + 7 * S) * 128 + c4];
        acc0.x += v0.x; acc0.y += v0.y; acc0.z += v0.z; acc0.w += v0.w;
        acc1.x += v1.x; acc1.y += v1.y; acc1.z += v1.z; acc1.w += v1.w;
        acc2.x += v2.x; acc2.y += v2.y; acc2.z += v2.z; acc2.w += v2.w;
        acc3.x += v3.x; acc3.y += v3.y; acc3.z += v3.z; acc3.w += v3.w;
        acc0.x += v4.x; acc0.y += v4.y; acc0.z += v4.z; acc0.w += v4.w;
        acc1.x += v5.x; acc1.y += v5.y; acc1.z += v5.z; acc1.w += v5.w;
        acc2.x += v6.x; acc2.y += v6.y; acc2.z += v6.z; acc2.w += v6.w;
        acc3.x += v7.x; acc3.y += v7.y; acc3.z += v7.z; acc3.w += v7.w;
    }
    for (; r < n_rows; r += S) {
        float4 v = Xv[(size_t)r * 128 + c4];
        acc0.x += v.x; acc0.y += v.y; acc0.z += v.z; acc0.w += v.w;
    }

    float4 s;
    s.x = (acc0.x + acc1.x) + (acc2.x + acc3.x);
    s.y = (acc0.y + acc1.y) + (acc2.y + acc3.y);
    s.z = (acc0.z + acc1.z) + (acc2.z + acc3.z);
    s.w = (acc0.w + acc1.w) + (acc2.w + acc3.w);

    __shared__ float4 red[WPB][128];
    red[g][c4] = s;
    __syncthreads();
    if (t < 128) {
        float4 tot = red[0][t];
        #pragma unroll
        for (int k = 1; k < WPB; k++) {
            float4 v = red[k][t];
            tot.x += v.x; tot.y += v.y; tot.z += v.z; tot.w += v.w;
        }
        ((float4*)g_scratch)[(size_t)blockIdx.x * 128 + t] = tot;
    }
}

// ---------------------------------------------------------------------------
// Kernel 2 (fused finalize): 64 blocks x 256 threads. Each block redundantly
// reduces the 303 KB L2-resident scratch -> agg in smem (~590 warp-LDGs),
// then 8 warps each compute one GRU output (3 gate dot products of 512).
// gh = b_hh since h = 0 (W_hh never read).
// ---------------------------------------------------------------------------
__global__ void __launch_bounds__(256) finalize_kernel(
    const float* __restrict__ W_ih,
    const float* __restrict__ b_ih,
    const float* __restrict__ b_hh,
    float* __restrict__ out,
    float inv_n)
{
    __shared__ float4 part[2][128];
    __shared__ float  agg[IN_DIM];
    const int t = threadIdx.x;

    // Phase A: reduce 148 partial rows. 2 row-phases x 128 columns.
    {
        const int c4 = t & 127;
        const int ty = t >> 7;       // 0..1
        const float4* __restrict__ sv = (const float4*)g_scratch;
        float4 s = make_float4(0.f, 0.f, 0.f, 0.f);
        #pragma unroll 4
        for (int p = ty; p < GRID1; p += 2) {
            float4 v = sv[p * 128 + c4];
            s.x += v.x; s.y += v.y; s.z += v.z; s.w += v.w;
        }
        part[ty][c4] = s;
    }
    __syncthreads();
    if (t < 128) {
        float4 a = part[0][t];
        float4 b = part[1][t];
        a.x = (a.x + b.x) * inv_n;
        a.y = (a.y + b.y) * inv_n;
        a.z = (a.z + b.z) * inv_n;
        a.w = (a.w + b.w) * inv_n;
        ((float4*)agg)[t] = a;
    }
    __syncthreads();

    // Phase B: one warp per output i. 64 blocks * 8 warps = 512 outputs.
    const int warp = t >> 5;
    const int lane = t & 31;
    const int i = blockIdx.x * 8 + warp;
    const float4* __restrict__ aggv = (const float4*)agg;

    float acc[3];
    #pragma unroll
    for (int g = 0; g < 3; g++) {
        const float4* __restrict__ row =
            (const float4*)(W_ih + (size_t)(g * HID + i) * IN_DIM);
        float a = 0.f;
        #pragma unroll
        for (int u = 0; u < 4; u++) {
            float4 w = row[lane + u * 32];
            float4 x = aggv[lane + u * 32];
            a += w.x * x.x + w.y * x.y + w.z * x.z + w.w * x.w;
        }
        #pragma unroll
        for (int off = 16; off; off >>= 1)
            a += __shfl_xor_sync(0xFFFFFFFFu, a, off);
        acc[g] = a;
    }

    if (lane == 0) {
        float gi_r = acc[0] + b_ih[i];
        float gi_z = acc[1] + b_ih[HID + i];
        float gi_n = acc[2] + b_ih[2 * HID + i];
        float r = 1.f / (1.f + __expf(-(gi_r + b_hh[i])));
        float z = 1.f / (1.f + __expf(-(gi_z + b_hh[HID + i])));
        float n = tanhf(gi_n + r * b_hh[2 * HID + i]);
        out[i] = (1.f - z) * n;   // + z*h with h=0
    }
}

extern "C" void kernel_launch(void* const* d_in, const int* in_sizes, int n_in,
                              void* d_out, int out_size) {
    const float* parent_states = (const float*)d_in[0];
    const float* weight_ih     = (const float*)d_in[1];
    // d_in[2] = weight_hh : unused (h = 0 -> W_hh @ h = 0)
    const float* bias_ih       = (const float*)d_in[3];
    const float* bias_hh       = (const float*)d_in[4];
    float* out = (float*)d_out;

    const int n_rows = in_sizes[0] / IN_DIM;
    const float inv_n = 1.0f / (float)n_rows;

    colsum_kernel<<<GRID1, BLK1>>>(parent_states, n_rows);
    finalize_kernel<<<64, 256>>>(weight_ih, bias_ih, bias_hh, out, inv_n);
}